// round 7
// baseline (speedup 1.0000x reference)
#include <cuda_runtime.h>
#include <cuda_fp16.h>
#include <mma.h>
#include <cstdint>

using namespace nvcuda;

#define NE 8
#define NTOK 8192
#define DDIM 1024
#define HDIM 2048
#define ODIM 1024
#define OUTC (ODIM + NE)   // 1032

#define BM 128
#define BN 128
#define BK 64
#define NTHREADS 256
#define NSTAGE 3

// smem strides in HALF elements
#define A_STRIDE 72        // 64 + 8 pad -> 144B rows
#define B_STRIDE 136       // 128 + 8 pad -> 272B rows
#define C_STRIDE 136       // floats
#define A_STAGE_BYTES (BM * A_STRIDE * 2)   // 18432
#define B_STAGE_BYTES (BK * B_STRIDE * 2)   // 17408
#define SMEM_A_OFF 0
#define SMEM_B_OFF (NSTAGE * A_STAGE_BYTES)                   // 55296
#define SMEM_STAGE_END (SMEM_B_OFF + NSTAGE * B_STAGE_BYTES)  // 107520
#define SMEM_C_BYTES (BM * C_STRIDE * 4)                      // 69632 (union w/ stages)
#define SMEM_PERM_OFF SMEM_STAGE_END                          // 107520
#define SMEM_BYTES (SMEM_PERM_OFF + BM * 4)                   // 108032

#define PERM_CAP (NTOK + NE * BM)   // 9216
#define MAXTILES (PERM_CAP / BM)    // 72

// ---- scratch (__device__ globals; no allocations allowed) ----
__device__ int    g_padoff[NE];
__device__ int    g_padcount[NE];
__device__ int    g_perm[PERM_CAP];
__device__ __half g_xh [(size_t)NTOK * DDIM];         // 16 MB
__device__ __half g_w1h[(size_t)NE * DDIM * HDIM];    // 32 MB
__device__ __half g_w2h[(size_t)NE * HDIM * ODIM];    // 32 MB
__device__ __half g_hh [(size_t)PERM_CAP * HDIM];     // 37.7 MB intermediate h (fp16)

// ---- cp.async helpers ----
__device__ __forceinline__ uint32_t smem_u32(const void* p) {
    uint32_t a;
    asm("{ .reg .u64 t; cvta.to.shared.u64 t, %1; cvt.u32.u64 %0, t; }" : "=r"(a) : "l"(p));
    return a;
}
__device__ __forceinline__ void cp16(uint32_t dst, const void* src) {
    asm volatile("cp.async.cg.shared.global [%0], [%1], 16;\n" :: "r"(dst), "l"(src));
}
#define CP_COMMIT() asm volatile("cp.async.commit_group;\n" ::: "memory")
#define CP_WAIT1()  asm volatile("cp.async.wait_group 1;\n" ::: "memory")

// ---------------- fused routing + onehot (single block) ----------------
__global__ void __launch_bounds__(1024) k_route(const int* __restrict__ eidx,
                                                float* __restrict__ out) {
    __shared__ int scount[NE];
    __shared__ int soff[NE];
    __shared__ int scursor[NE];
    int tid = threadIdx.x;

    if (tid < NE) scount[tid] = 0;
    __syncthreads();

    for (int n = tid; n < NTOK; n += 1024) atomicAdd(&scount[eidx[n]], 1);
    __syncthreads();

    if (tid == 0) {
        int acc = 0;
        for (int e = 0; e < NE; e++) {
            int c = scount[e];
            int pc = ((c + BM - 1) / BM) * BM;
            soff[e] = acc; scursor[e] = acc;
            g_padoff[e] = acc; g_padcount[e] = pc;
            acc += pc;
        }
    }
    __syncthreads();

    // sentinel-fill ONLY padding slots [off+count, off+padcount)
    {
        int e = tid >> 7;
        int l = tid & 127;
        int c  = scount[e];
        int pc = g_padcount[e];
        for (int i = c + l; i < pc; i += 128) g_perm[soff[e] + i] = -1;
    }

    // scatter + onehot tail columns
    for (int n = tid; n < NTOK; n += 1024) {
        int e = eidx[n];
        int p = atomicAdd(&scursor[e], 1);
        g_perm[p] = n;
        float4 lo = make_float4(e == 0 ? 1.f : 0.f, e == 1 ? 1.f : 0.f,
                                e == 2 ? 1.f : 0.f, e == 3 ? 1.f : 0.f);
        float4 hi = make_float4(e == 4 ? 1.f : 0.f, e == 5 ? 1.f : 0.f,
                                e == 6 ? 1.f : 0.f, e == 7 ? 1.f : 0.f);
        float* row = out + (size_t)n * OUTC + ODIM;
        *reinterpret_cast<float4*>(row)     = lo;
        *reinterpret_cast<float4*>(row + 4) = hi;
    }
}

// ---------------- fused fp32 -> fp16 conversion (8 floats/thread, 16B stores) ----------------
#define N8_X  ((size_t)NTOK * DDIM / 8)          // 1,048,576
#define N8_W1 ((size_t)NE * DDIM * HDIM / 8)     // 2,097,152
#define N8_W2 ((size_t)NE * HDIM * ODIM / 8)     // 2,097,152
#define N8_TOTAL (N8_X + N8_W1 + N8_W2)

__global__ void k_cvt_all(const float* __restrict__ x,
                          const float* __restrict__ W1,
                          const float* __restrict__ W2) {
    size_t i = (size_t)blockIdx.x * blockDim.x + threadIdx.x;
    if (i >= N8_TOTAL) return;
    const float* src;
    __half* dst;
    size_t j;
    if (i < N8_X)              { src = x;  dst = g_xh;  j = i; }
    else if (i < N8_X + N8_W1) { src = W1; dst = g_w1h; j = i - N8_X; }
    else                       { src = W2; dst = g_w2h; j = i - N8_X - N8_W1; }
    float4 v0 = reinterpret_cast<const float4*>(src)[2 * j];
    float4 v1 = reinterpret_cast<const float4*>(src)[2 * j + 1];
    __half2 h0 = __floats2half2_rn(v0.x, v0.y);
    __half2 h1 = __floats2half2_rn(v0.z, v0.w);
    __half2 h2 = __floats2half2_rn(v1.x, v1.y);
    __half2 h3 = __floats2half2_rn(v1.z, v1.w);
    uint4 pk;
    pk.x = *reinterpret_cast<uint32_t*>(&h0);
    pk.y = *reinterpret_cast<uint32_t*>(&h1);
    pk.z = *reinterpret_cast<uint32_t*>(&h2);
    pk.w = *reinterpret_cast<uint32_t*>(&h3);
    reinterpret_cast<uint4*>(dst)[j] = pk;
}

// ---------------- fragments ----------------
using FragA = wmma::fragment<wmma::matrix_a, 16, 16, 16, __half, wmma::row_major>;
using FragB = wmma::fragment<wmma::matrix_b, 16, 16, 16, __half, wmma::row_major>;
using FragC = wmma::fragment<wmma::accumulator, 16, 16, 16, float>;

// ---------------- fp16 grouped GEMM (BK=64, 3-stage, one barrier per K-step) ----------------
template<int KDIM, int WLD, bool GATHER, bool SCATTER>
__global__ void __launch_bounds__(NTHREADS, 2) k_gemm(
    const float* __restrict__ bias, float* __restrict__ dst)
{
    int e    = blockIdx.z;
    int rows = g_padcount[e];
    int row0 = blockIdx.y * BM;
    if (row0 >= rows) return;
    int base = g_padoff[e];
    int n0   = blockIdx.x * BN;

    const __half* __restrict__ Asrc = GATHER ? g_xh : g_hh;
    const __half* __restrict__ Wb   = (GATHER ? g_w1h : g_w2h) + (size_t)e * KDIM * WLD;
    const float*  __restrict__ be   = bias + (size_t)e * WLD;

    extern __shared__ char smem[];
    uint32_t smem_base = smem_u32(smem);
    int* sperm = (int*)(smem + SMEM_PERM_OFF);
    float* sC  = (float*)smem;

    int tid  = threadIdx.x;
    int warp = tid >> 5;
    int wr   = warp >> 1;   // 0..3: 32-row band
    int wc   = warp & 1;    // 0..1: 64-col band

    if (tid < BM) sperm[tid] = g_perm[base + row0 + tid];
    __syncthreads();

    FragC acc[2][4];
    #pragma unroll
    for (int i = 0; i < 2; i++)
        #pragma unroll
        for (int j = 0; j < 4; j++)
            wmma::fill_fragment(acc[i][j], 0.0f);

    const int KT = KDIM / BK;

    auto load_stage = [&](int st) {
        if (st < KT) {
            int k0  = st * BK;
            int buf = st % NSTAGE;
            uint32_t aB = smem_base + SMEM_A_OFF + buf * A_STAGE_BYTES;
            uint32_t bB = smem_base + SMEM_B_OFF + buf * B_STAGE_BYTES;
            #pragma unroll
            for (int i = 0; i < 4; i++) {          // A: 128 rows x 64 halves = 1024 x 16B
                int lin = i * NTHREADS + tid;
                int r = lin >> 3, c8 = lin & 7;
                const __half* src;
                if (GATHER) {
                    int t = sperm[r]; if (t < 0) t = 0;
                    src = Asrc + (size_t)t * KDIM + k0 + c8 * 8;
                } else {
                    src = Asrc + (size_t)(base + row0 + r) * KDIM + k0 + c8 * 8;
                }
                cp16(aB + r * (A_STRIDE * 2) + c8 * 16, src);
            }
            #pragma unroll
            for (int i = 0; i < 4; i++) {          // B: 64 rows x 128 halves = 1024 x 16B
                int lin = i * NTHREADS + tid;
                int r = lin >> 4, c8 = lin & 15;
                cp16(bB + r * (B_STRIDE * 2) + c8 * 16,
                     Wb + (size_t)(k0 + r) * WLD + n0 + c8 * 8);
            }
        }
        CP_COMMIT();
    };

    // preload 2 stages (3rd buffer free)
    load_stage(0); load_stage(1);

    for (int s = 0; s < KT; s++) {
        CP_WAIT1();                  // <=1 newer group pending -> stage s resident (this thread)
        __syncthreads();             // all threads' stage-s copies visible; compute(s-1) done
        load_stage(s + 2);           // buf (s+2)%3 == (s-1)%3 — proven drained by the barrier
        int buf = s % NSTAGE;
        const __half* A0 = (const __half*)(smem + SMEM_A_OFF + buf * A_STAGE_BYTES);
        const __half* B0 = (const __half*)(smem + SMEM_B_OFF + buf * B_STAGE_BYTES);
        #pragma unroll
        for (int kk = 0; kk < BK; kk += 16) {
            FragA a[2];
            FragB b[4];
            wmma::load_matrix_sync(a[0], A0 + (wr * 32 +  0) * A_STRIDE + kk, A_STRIDE);
            wmma::load_matrix_sync(a[1], A0 + (wr * 32 + 16) * A_STRIDE + kk, A_STRIDE);
            #pragma unroll
            for (int j = 0; j < 4; j++)
                wmma::load_matrix_sync(b[j], B0 + kk * B_STRIDE + wc * 64 + j * 16, B_STRIDE);
            #pragma unroll
            for (int i = 0; i < 2; i++)
                #pragma unroll
                for (int j = 0; j < 4; j++)
                    wmma::mma_sync(acc[i][j], a[i], b[j], acc[i][j]);
        }
    }

    // ---- epilogue: stage C in smem (union over stage buffers) ----
    __syncthreads();
    #pragma unroll
    for (int i = 0; i < 2; i++)
        #pragma unroll
        for (int j = 0; j < 4; j++)
            wmma::store_matrix_sync(sC + (wr * 32 + i * 16) * C_STRIDE + wc * 64 + j * 16,
                                    acc[i][j], C_STRIDE, wmma::mem_row_major);
    __syncthreads();

    #pragma unroll
    for (int i = 0; i < 16; i++) {              // 128x128 = 4096 float4 chunks
        int lin = i * NTHREADS + tid;
        int r   = lin >> 5;
        int c4  = lin & 31;
        int t   = sperm[r];
        float4 v = *reinterpret_cast<const float4*>(sC + r * C_STRIDE + c4 * 4);
        const float4 bb = *reinterpret_cast<const float4*>(&be[n0 + c4 * 4]);
        v.x += bb.x; v.y += bb.y; v.z += bb.z; v.w += bb.w;
        if (SCATTER) {
            if (t >= 0) {
                *reinterpret_cast<float4*>(&dst[(size_t)t * OUTC + n0 + c4 * 4]) = v;
            }
        } else {
            __half2 lo = __floats2half2_rn(v.x, v.y);
            __half2 hi = __floats2half2_rn(v.z, v.w);
            uint32_t* p = reinterpret_cast<uint32_t*>(
                g_hh + (size_t)(base + row0 + r) * WLD + n0 + c4 * 4);
            p[0] = *reinterpret_cast<uint32_t*>(&lo);
            p[1] = *reinterpret_cast<uint32_t*>(&hi);
        }
    }
}

// ---------------- launch ----------------
extern "C" void kernel_launch(void* const* d_in, const int* in_sizes, int n_in,
                              void* d_out, int out_size) {
    const float* x    = (const float*)d_in[0];
    const float* W1   = (const float*)d_in[1];
    const float* b1   = (const float*)d_in[2];
    const float* W2   = (const float*)d_in[3];
    const float* b2   = (const float*)d_in[4];
    const int*   eidx = (const int*)  d_in[5];
    float* out = (float*)d_out;

    cudaFuncSetAttribute(k_gemm<DDIM, HDIM, true, false>,
                         cudaFuncAttributeMaxDynamicSharedMemorySize, SMEM_BYTES);
    cudaFuncSetAttribute(k_gemm<HDIM, ODIM, false, true>,
                         cudaFuncAttributeMaxDynamicSharedMemorySize, SMEM_BYTES);

    k_route<<<1, 1024>>>(eidx, out);
    k_cvt_all<<<(int)((N8_TOTAL + 255) / 256), 256>>>(x, W1, W2);

    dim3 g1(HDIM / BN, MAXTILES, NE);   // (16, 72, 8)
    k_gemm<DDIM, HDIM, true, false><<<g1, NTHREADS, SMEM_BYTES>>>(b1, nullptr);

    dim3 g2(ODIM / BN, MAXTILES, NE);   // (8, 72, 8)
    k_gemm<HDIM, ODIM, false, true><<<g2, NTHREADS, SMEM_BYTES>>>(b2, out);
}